// round 3
// baseline (speedup 1.0000x reference)
#include <cuda_runtime.h>
#include <math.h>

#define D_MODEL 2048
#define N_HEADS 16
#define HEAD_DIM 128
#define D_FF    8192
#define BATCHSZ 2
#define SEQLEN  2048
#define M_TOK   (BATCHSZ * SEQLEN)   // 4096

// ---------------- scratch (device globals; no allocation allowed) ----------
__device__ float g_h  [(size_t)M_TOK * D_MODEL];
__device__ float g_qkv[(size_t)M_TOK * 3 * D_MODEL];
__device__ float g_y  [(size_t)M_TOK * D_MODEL];
__device__ float g_x1 [(size_t)M_TOK * D_MODEL];
__device__ float g_h2 [(size_t)M_TOK * D_MODEL];
__device__ float g_m  [(size_t)M_TOK * D_FF];

// ---------------- helpers ---------------------------------------------------
__device__ __forceinline__ float gelu_exact(float v) {
    return 0.5f * v * (1.0f + erff(v * 0.70710678118654752440f));
}

// ---------------- LayerNorm: one block per row (2048 elems, 256 thr) --------
__global__ void ln_kernel(const float* __restrict__ x,
                          const float* __restrict__ w,
                          const float* __restrict__ b,
                          float* __restrict__ out) {
    const int row = blockIdx.x;
    const int tid = threadIdx.x;
    const float4* xr = (const float4*)(x + (size_t)row * D_MODEL);
    float4 v0 = xr[tid];
    float4 v1 = xr[tid + 256];
    float s  = v0.x + v0.y + v0.z + v0.w + v1.x + v1.y + v1.z + v1.w;
    float ss = v0.x*v0.x + v0.y*v0.y + v0.z*v0.z + v0.w*v0.w
             + v1.x*v1.x + v1.y*v1.y + v1.z*v1.z + v1.w*v1.w;

    __shared__ float shs[8], shq[8];
    #pragma unroll
    for (int o = 16; o > 0; o >>= 1) {
        s  += __shfl_xor_sync(0xffffffffu, s,  o);
        ss += __shfl_xor_sync(0xffffffffu, ss, o);
    }
    if ((tid & 31) == 0) { shs[tid >> 5] = s; shq[tid >> 5] = ss; }
    __syncthreads();
    if (tid == 0) {
        float ts = 0.f, tq = 0.f;
        #pragma unroll
        for (int j = 0; j < 8; j++) { ts += shs[j]; tq += shq[j]; }
        float mean = ts * (1.0f / D_MODEL);
        float var  = tq * (1.0f / D_MODEL) - mean * mean;
        shs[0] = mean;
        shq[0] = rsqrtf(var + 1e-5f);
    }
    __syncthreads();
    const float mean = shs[0];
    const float inv  = shq[0];

    const float4* w4 = (const float4*)w;
    const float4* b4 = (const float4*)b;
    float4* o4 = (float4*)(out + (size_t)row * D_MODEL);
    #pragma unroll
    for (int i = 0; i < 2; i++) {
        int idx = tid + i * 256;
        float4 v = i ? v1 : v0;
        float4 ww = w4[idx], bb = b4[idx], r;
        r.x = (v.x - mean) * inv * ww.x + bb.x;
        r.y = (v.y - mean) * inv * ww.y + bb.y;
        r.z = (v.z - mean) * inv * ww.z + bb.z;
        r.w = (v.w - mean) * inv * ww.w + bb.w;
        o4[idx] = r;
    }
}

// ---------------- fused causal flash attention ------------------------------
// One CTA handles BQ=64 query rows for one (b,h). 256 threads.
// Thread t owns query row (t/4) and dim chunk (t%4)*32. The 4 threads of a
// row form a quad (consecutive lanes in one warp); score partial dots are
// reduced across the quad via shfl, after which ALL quad lanes hold the full
// probability row in registers (no shared staging needed).
#define BQ 64
#define BKV 64
__global__ __launch_bounds__(256, 1)
void flash_attn(const float* __restrict__ qkv, float* __restrict__ y) {
    const int qt = blockIdx.x;            // query tile index
    const int z  = blockIdx.y;            // b*H + h
    const int zb = z >> 4, zh = z & 15;
    const int tid = threadIdx.x;
    const int qr  = tid >> 2;             // 0..63 query row in tile
    const int dq  = (tid & 3) * 32;       // dim chunk base (32 floats)

    const long long baseQ = (long long)zb * SEQLEN * 3 * D_MODEL + zh * HEAD_DIM;
    const float* Q = qkv + baseQ;
    const float* K = qkv + baseQ + D_MODEL;
    const float* V = qkv + baseQ + 2 * D_MODEL;

    const int q_global = qt * BQ + qr;

    // Load my 32 dims of my query row into registers, pre-scaled.
    float qreg[32];
    {
        const float* qp = Q + (long long)q_global * (3 * D_MODEL) + dq;
        #pragma unroll
        for (int i = 0; i < 32; i += 4) {
            float4 v = *(const float4*)(qp + i);
            qreg[i+0] = v.x * 0.08838834764831845f;
            qreg[i+1] = v.y * 0.08838834764831845f;
            qreg[i+2] = v.z * 0.08838834764831845f;
            qreg[i+3] = v.w * 0.08838834764831845f;
        }
    }

    float acc[32];
    #pragma unroll
    for (int i = 0; i < 32; i++) acc[i] = 0.f;
    float m_run = -1e30f, l_run = 0.f;

    __shared__ float Ks[BKV][HEAD_DIM];       // 32 KB
    __shared__ float Vs[BKV][HEAD_DIM];       // 32 KB

    const int kv_tiles = qt + 1;              // causal: only tiles <= qt
    for (int t = 0; t < kv_tiles; t++) {
        // cooperative load of K,V tile: 64 rows x 128 cols, 256 threads
        {
            const int lr = tid >> 2;                  // 0..63 row
            const int lc = (tid & 3) * 32;            // col base
            const long long roff = (long long)(t * BKV + lr) * (3 * D_MODEL) + lc;
            #pragma unroll
            for (int i = 0; i < 32; i += 4) {
                *(float4*)&Ks[lr][lc + i] = *(const float4*)(K + roff + i);
                *(float4*)&Vs[lr][lc + i] = *(const float4*)(V + roff + i);
            }
        }
        __syncthreads();

        // scores: each thread computes partial dot over its 32 dims for all
        // 64 keys, reduced across the quad via shfl.
        const bool diag = (t == qt);
        float pmax = -1e30f;
        float pv[64];
        #pragma unroll 8
        for (int j = 0; j < BKV; j++) {
            float s = 0.f;
            const float* kr = &Ks[j][dq];
            #pragma unroll
            for (int i = 0; i < 32; i++) s += qreg[i] * kr[i];
            // quad reduce (4 consecutive lanes of one warp)
            s += __shfl_xor_sync(0xffffffffu, s, 1);
            s += __shfl_xor_sync(0xffffffffu, s, 2);
            if (diag && (t * BKV + j) > q_global) s = -1e30f;
            pv[j] = s;
            pmax = fmaxf(pmax, s);
        }
        // online softmax update (per-row state identical across quad)
        float m_new = fmaxf(m_run, pmax);
        float corr  = __expf(m_run - m_new);
        float psum = 0.f;
        #pragma unroll 8
        for (int j = 0; j < BKV; j++) {
            float p = __expf(pv[j] - m_new);
            pv[j] = p;
            psum += p;
        }
        l_run = l_run * corr + psum;
        m_run = m_new;

        // acc update: acc = acc*corr + P_row @ V_tile  (my 32 dims)
        #pragma unroll
        for (int i = 0; i < 32; i++) acc[i] *= corr;
        #pragma unroll 4
        for (int j = 0; j < BKV; j++) {
            const float p = pv[j];
            const float* vr = &Vs[j][dq];
            #pragma unroll
            for (int i = 0; i < 32; i++) acc[i] += p * vr[i];
        }
        __syncthreads();
    }

    // write output: y[b, s, h*128 + d]
    const float inv = 1.0f / l_run;
    float* yp = y + ((long long)zb * SEQLEN + qt * BQ + qr) * D_MODEL + zh * HEAD_DIM + dq;
    #pragma unroll
    for (int i = 0; i < 32; i += 4) {
        float4 v;
        v.x = acc[i+0] * inv; v.y = acc[i+1] * inv;
        v.z = acc[i+2] * inv; v.w = acc[i+3] * inv;
        *(float4*)(yp + i) = v;
    }
}

// ---------------- NT GEMM: C = A(MxK) * B(NxK)^T (+epi) ---------------------
// EPI: 0 = none, 1 = +bias, 2 = +bias+residual, 3 = +bias+gelu
template<int EPI>
__global__ __launch_bounds__(256, 2)
void gemm_nt(const float* __restrict__ A, const float* __restrict__ B,
             float* __restrict__ C, const float* __restrict__ bias,
             const float* __restrict__ Resid,
             int K, int ldc) {
    constexpr int BM = 128, BN = 128, BK = 16, TM = 8, TN = 8;
    const int lda = K, ldb = K;

    A += (size_t)blockIdx.y * BM * lda;
    B += (size_t)blockIdx.x * BN * ldb;
    const size_t coff = (size_t)blockIdx.y * BM * ldc + (size_t)blockIdx.x * BN;
    C += coff;
    if (EPI == 2) Resid += coff;
    if (EPI >= 1) bias += (size_t)blockIdx.x * BN;

    __shared__ float As[BK][BM];
    __shared__ float Bs[BK][BN];

    const int tid = threadIdx.x;
    const int tx = tid & 15, ty = tid >> 4;
    const int lr = tid >> 2;          // 0..63
    const int lk = (tid & 3) << 2;    // 0,4,8,12

    float acc[TM][TN];
    #pragma unroll
    for (int m = 0; m < TM; m++)
        #pragma unroll
        for (int n = 0; n < TN; n++) acc[m][n] = 0.f;

    for (int k0 = 0; k0 < K; k0 += BK) {
        #pragma unroll
        for (int i = 0; i < 2; i++) {
            const int r = lr + i * 64;
            float4 a = *(const float4*)(A + (size_t)r * lda + k0 + lk);
            As[lk + 0][r] = a.x; As[lk + 1][r] = a.y;
            As[lk + 2][r] = a.z; As[lk + 3][r] = a.w;
            float4 b = *(const float4*)(B + (size_t)r * ldb + k0 + lk);
            Bs[lk + 0][r] = b.x; Bs[lk + 1][r] = b.y;
            Bs[lk + 2][r] = b.z; Bs[lk + 3][r] = b.w;
        }
        __syncthreads();
        #pragma unroll
        for (int k = 0; k < BK; k++) {
            float4 a0 = *(const float4*)&As[k][ty * TM];
            float4 a1 = *(const float4*)&As[k][ty * TM + 4];
            float4 b0 = *(const float4*)&Bs[k][tx * TN];
            float4 b1 = *(const float4*)&Bs[k][tx * TN + 4];
            float ra[8] = {a0.x, a0.y, a0.z, a0.w, a1.x, a1.y, a1.z, a1.w};
            float rb[8] = {b0.x, b0.y, b0.z, b0.w, b1.x, b1.y, b1.z, b1.w};
            #pragma unroll
            for (int m = 0; m < TM; m++)
                #pragma unroll
                for (int n = 0; n < TN; n++) acc[m][n] += ra[m] * rb[n];
        }
        __syncthreads();
    }

    #pragma unroll
    for (int m = 0; m < TM; m++) {
        const int r = ty * TM + m;
        float* crow = C + (size_t)r * ldc + tx * TN;
        const float* rrow = (EPI == 2) ? (Resid + (size_t)r * ldc + tx * TN) : nullptr;
        #pragma unroll
        for (int n = 0; n < TN; n += 4) {
            float4 v;
            v.x = acc[m][n + 0];
            v.y = acc[m][n + 1];
            v.z = acc[m][n + 2];
            v.w = acc[m][n + 3];
            if (EPI >= 1) {
                v.x += bias[tx * TN + n + 0];
                v.y += bias[tx * TN + n + 1];
                v.z += bias[tx * TN + n + 2];
                v.w += bias[tx * TN + n + 3];
            }
            if (EPI == 2) {
                v.x += rrow[n + 0]; v.y += rrow[n + 1];
                v.z += rrow[n + 2]; v.w += rrow[n + 3];
            }
            if (EPI == 3) {
                v.x = gelu_exact(v.x); v.y = gelu_exact(v.y);
                v.z = gelu_exact(v.z); v.w = gelu_exact(v.w);
            }
            *(float4*)(crow + n) = v;
        }
    }
}

// ---------------- driver -----------------------------------------------------
extern "C" void kernel_launch(void* const* d_in, const int* in_sizes, int n_in,
                              void* d_out, int out_size) {
    (void)in_sizes; (void)n_in; (void)out_size;
    const float* x     = (const float*)d_in[0];
    const float* ln1_w = (const float*)d_in[1];
    const float* ln1_b = (const float*)d_in[2];
    const float* qkv_w = (const float*)d_in[3];
    const float* qkv_b = (const float*)d_in[4];
    const float* out_w = (const float*)d_in[5];
    const float* out_b = (const float*)d_in[6];
    const float* ln2_w = (const float*)d_in[7];
    const float* ln2_b = (const float*)d_in[8];
    const float* w1    = (const float*)d_in[9];
    const float* b1    = (const float*)d_in[10];
    const float* w2    = (const float*)d_in[11];
    const float* b2    = (const float*)d_in[12];
    float* out = (float*)d_out;

    float *h, *qkv, *y, *x1, *h2, *mm;
    cudaGetSymbolAddress((void**)&h,   g_h);
    cudaGetSymbolAddress((void**)&qkv, g_qkv);
    cudaGetSymbolAddress((void**)&y,   g_y);
    cudaGetSymbolAddress((void**)&x1,  g_x1);
    cudaGetSymbolAddress((void**)&h2,  g_h2);
    cudaGetSymbolAddress((void**)&mm,  g_m);

    // 1. LN1
    ln_kernel<<<M_TOK, 256>>>(x, ln1_w, ln1_b, h);
    // 2. QKV = h @ qkv_w^T + qkv_b
    gemm_nt<1><<<dim3(3 * D_MODEL / 128, M_TOK / 128), 256>>>(
        h, qkv_w, qkv, qkv_b, nullptr, D_MODEL, 3 * D_MODEL);
    // 3-5. fused causal attention -> y in [B,S,H*Dh] layout
    flash_attn<<<dim3(SEQLEN / BQ, BATCHSZ * N_HEADS), 256>>>(qkv, y);
    // 6. x1 = x + y @ out_w^T + out_b
    gemm_nt<2><<<dim3(D_MODEL / 128, M_TOK / 128), 256>>>(
        y, out_w, x1, out_b, x, D_MODEL, D_MODEL);
    // 7. LN2
    ln_kernel<<<M_TOK, 256>>>(x1, ln2_w, ln2_b, h2);
    // 8. m = gelu(h2 @ w1^T + b1)
    gemm_nt<3><<<dim3(D_FF / 128, M_TOK / 128), 256>>>(
        h2, w1, mm, b1, nullptr, D_MODEL, D_FF);
    // 9. out = x1 + m @ w2^T + b2
    gemm_nt<2><<<dim3(D_MODEL / 128, M_TOK / 128), 256>>>(
        mm, w2, out, b2, x1, D_FF, D_MODEL);
}

// round 13
// speedup vs baseline: 1.5558x; 1.5558x over previous
#include <cuda_runtime.h>
#include <math.h>

#define D_MODEL 2048
#define N_HEADS 16
#define HEAD_DIM 128
#define D_FF    8192
#define BATCHSZ 2
#define SEQLEN  2048
#define M_TOK   (BATCHSZ * SEQLEN)   // 4096

// ---------------- scratch (device globals; no allocation allowed) ----------
__device__ float g_h  [(size_t)M_TOK * D_MODEL];
__device__ float g_qkv[(size_t)M_TOK * 3 * D_MODEL];
__device__ float g_y  [(size_t)M_TOK * D_MODEL];
__device__ float g_x1 [(size_t)M_TOK * D_MODEL];
__device__ float g_h2 [(size_t)M_TOK * D_MODEL];
__device__ float g_m  [(size_t)M_TOK * D_FF];

// ---------------- helpers ---------------------------------------------------
__device__ __forceinline__ float gelu_exact(float v) {
    return 0.5f * v * (1.0f + erff(v * 0.70710678118654752440f));
}
__device__ __forceinline__ unsigned f2tf(float f) {
    unsigned u; asm("cvt.rna.tf32.f32 %0, %1;" : "=r"(u) : "f"(f)); return u;
}
__device__ __forceinline__ unsigned smem_u32(const void* p) {
    return (unsigned)__cvta_generic_to_shared(p);
}
__device__ __forceinline__ void ldmx4(unsigned& r0, unsigned& r1, unsigned& r2,
                                      unsigned& r3, unsigned addr) {
    asm volatile("ldmatrix.sync.aligned.m8n8.x4.shared.b16 {%0,%1,%2,%3}, [%4];"
                 : "=r"(r0), "=r"(r1), "=r"(r2), "=r"(r3) : "r"(addr));
}
__device__ __forceinline__ void mma_tf32(float* d, const unsigned* a, const unsigned* b) {
    asm volatile(
        "mma.sync.aligned.m16n8k8.row.col.f32.tf32.tf32.f32 "
        "{%0,%1,%2,%3}, {%4,%5,%6,%7}, {%8,%9}, {%0,%1,%2,%3};"
        : "+f"(d[0]), "+f"(d[1]), "+f"(d[2]), "+f"(d[3])
        : "r"(a[0]), "r"(a[1]), "r"(a[2]), "r"(a[3]), "r"(b[0]), "r"(b[1]));
}

// ---------------- LayerNorm: one block per row (2048 elems, 256 thr) --------
__global__ void ln_kernel(const float* __restrict__ x,
                          const float* __restrict__ w,
                          const float* __restrict__ b,
                          float* __restrict__ out) {
    const int row = blockIdx.x;
    const int tid = threadIdx.x;
    const float4* xr = (const float4*)(x + (size_t)row * D_MODEL);
    float4 v0 = xr[tid];
    float4 v1 = xr[tid + 256];
    float s  = v0.x + v0.y + v0.z + v0.w + v1.x + v1.y + v1.z + v1.w;
    float ss = v0.x*v0.x + v0.y*v0.y + v0.z*v0.z + v0.w*v0.w
             + v1.x*v1.x + v1.y*v1.y + v1.z*v1.z + v1.w*v1.w;

    __shared__ float shs[8], shq[8];
    #pragma unroll
    for (int o = 16; o > 0; o >>= 1) {
        s  += __shfl_xor_sync(0xffffffffu, s,  o);
        ss += __shfl_xor_sync(0xffffffffu, ss, o);
    }
    if ((tid & 31) == 0) { shs[tid >> 5] = s; shq[tid >> 5] = ss; }
    __syncthreads();
    if (tid == 0) {
        float ts = 0.f, tq = 0.f;
        #pragma unroll
        for (int j = 0; j < 8; j++) { ts += shs[j]; tq += shq[j]; }
        float mean = ts * (1.0f / D_MODEL);
        float var  = tq * (1.0f / D_MODEL) - mean * mean;
        shs[0] = mean;
        shq[0] = rsqrtf(var + 1e-5f);
    }
    __syncthreads();
    const float mean = shs[0];
    const float inv  = shq[0];

    const float4* w4 = (const float4*)w;
    const float4* b4 = (const float4*)b;
    float4* o4 = (float4*)(out + (size_t)row * D_MODEL);
    #pragma unroll
    for (int i = 0; i < 2; i++) {
        int idx = tid + i * 256;
        float4 v = i ? v1 : v0;
        float4 ww = w4[idx], bb = b4[idx], r;
        r.x = (v.x - mean) * inv * ww.x + bb.x;
        r.y = (v.y - mean) * inv * ww.y + bb.y;
        r.z = (v.z - mean) * inv * ww.z + bb.z;
        r.w = (v.w - mean) * inv * ww.w + bb.w;
        o4[idx] = r;
    }
}

// ---------------- fused causal flash attention (fp32, HW-validated R3) ------
#define BQ 64
#define BKV 64
__global__ __launch_bounds__(256, 1)
void flash_attn(const float* __restrict__ qkv, float* __restrict__ y) {
    const int qt = blockIdx.x;
    const int z  = blockIdx.y;
    const int zb = z >> 4, zh = z & 15;
    const int tid = threadIdx.x;
    const int qr  = tid >> 2;
    const int dq  = (tid & 3) * 32;

    const long long baseQ = (long long)zb * SEQLEN * 3 * D_MODEL + zh * HEAD_DIM;
    const float* Q = qkv + baseQ;
    const float* K = qkv + baseQ + D_MODEL;
    const float* V = qkv + baseQ + 2 * D_MODEL;

    const int q_global = qt * BQ + qr;

    float qreg[32];
    {
        const float* qp = Q + (long long)q_global * (3 * D_MODEL) + dq;
        #pragma unroll
        for (int i = 0; i < 32; i += 4) {
            float4 v = *(const float4*)(qp + i);
            qreg[i+0] = v.x * 0.08838834764831845f;
            qreg[i+1] = v.y * 0.08838834764831845f;
            qreg[i+2] = v.z * 0.08838834764831845f;
            qreg[i+3] = v.w * 0.08838834764831845f;
        }
    }

    float acc[32];
    #pragma unroll
    for (int i = 0; i < 32; i++) acc[i] = 0.f;
    float m_run = -1e30f, l_run = 0.f;

    __shared__ float Ks[BKV][HEAD_DIM];
    __shared__ float Vs[BKV][HEAD_DIM];

    const int kv_tiles = qt + 1;
    for (int t = 0; t < kv_tiles; t++) {
        {
            const int lr = tid >> 2;
            const int lc = (tid & 3) * 32;
            const long long roff = (long long)(t * BKV + lr) * (3 * D_MODEL) + lc;
            #pragma unroll
            for (int i = 0; i < 32; i += 4) {
                *(float4*)&Ks[lr][lc + i] = *(const float4*)(K + roff + i);
                *(float4*)&Vs[lr][lc + i] = *(const float4*)(V + roff + i);
            }
        }
        __syncthreads();

        const bool diag = (t == qt);
        float pmax = -1e30f;
        float pv[64];
        #pragma unroll 8
        for (int j = 0; j < BKV; j++) {
            float s = 0.f;
            const float* kr = &Ks[j][dq];
            #pragma unroll
            for (int i = 0; i < 32; i++) s += qreg[i] * kr[i];
            s += __shfl_xor_sync(0xffffffffu, s, 1);
            s += __shfl_xor_sync(0xffffffffu, s, 2);
            if (diag && (t * BKV + j) > q_global) s = -1e30f;
            pv[j] = s;
            pmax = fmaxf(pmax, s);
        }
        float m_new = fmaxf(m_run, pmax);
        float corr  = __expf(m_run - m_new);
        float psum = 0.f;
        #pragma unroll 8
        for (int j = 0; j < BKV; j++) {
            float p = __expf(pv[j] - m_new);
            pv[j] = p;
            psum += p;
        }
        l_run = l_run * corr + psum;
        m_run = m_new;

        #pragma unroll
        for (int i = 0; i < 32; i++) acc[i] *= corr;
        #pragma unroll 4
        for (int j = 0; j < BKV; j++) {
            const float p = pv[j];
            const float* vr = &Vs[j][dq];
            #pragma unroll
            for (int i = 0; i < 32; i++) acc[i] += p * vr[i];
        }
        __syncthreads();
    }

    const float inv = 1.0f / l_run;
    float* yp = y + ((long long)zb * SEQLEN + qt * BQ + qr) * D_MODEL + zh * HEAD_DIM + dq;
    #pragma unroll
    for (int i = 0; i < 32; i += 4) {
        float4 v;
        v.x = acc[i+0] * inv; v.y = acc[i+1] * inv;
        v.z = acc[i+2] * inv; v.w = acc[i+3] * inv;
        *(float4*)(yp + i) = v;
    }
}

// ---------------- TF32 tensor-core NT GEMM ----------------------------------
// C(MxN) = A(MxK) @ B(NxK)^T  (+epilogue). 128x128 tile, BK=16, 8 warps in
// 2(M) x 4(N); each warp computes 64x32 via m16n8k8 tf32 mma.
// Smem: A m-major [128][20], B n-major [128][20] (pad 4 -> conflict-free
// ldmatrix: 80B row stride covers all 32 banks).
// EPI: 0 none, 1 +bias, 2 +bias+residual, 3 +bias+gelu
template<int EPI>
__global__ __launch_bounds__(256, 2)
void gemm_nt_tc(const float* __restrict__ A, const float* __restrict__ B,
                float* __restrict__ C, const float* __restrict__ bias,
                const float* __restrict__ Resid,
                int K, int ldc) {
    constexpr int BM = 128, BN = 128, BK = 16, BKP = 20;
    __shared__ unsigned As[BM][BKP];
    __shared__ unsigned Bs[BN][BKP];

    const int tid  = threadIdx.x;
    const int lane = tid & 31;
    const int wid  = tid >> 5;
    const int wm   = (wid & 1) * 64;      // warp M offset
    const int wn   = (wid >> 1) * 32;     // warp N offset

    const float* Ag = A + (size_t)blockIdx.y * BM * K;
    const float* Bg = B + (size_t)blockIdx.x * BN * K;
    const size_t coff = (size_t)blockIdx.y * BM * ldc + (size_t)blockIdx.x * BN;
    C += coff;
    if (EPI == 2) Resid += coff;
    const float* biasp = (EPI >= 1) ? bias + (size_t)blockIdx.x * BN : nullptr;

    // global-load assignment: rows lr, lr+64; cols lc..lc+3
    const int lr = tid >> 2;
    const int lc = (tid & 3) * 4;

    // ldmatrix source addressing
    const int arow  = wm + (lane & 7) + ((lane >> 3) & 1) * 8;
    const int acolo = (lane >> 4) * 4;
    const int brow  = wn + (lane & 7) + (lane >> 4) * 8;
    const int bcolo = ((lane >> 3) & 1) * 4;

    float acc[4][4][4];
    #pragma unroll
    for (int mt = 0; mt < 4; mt++)
        #pragma unroll
        for (int nt = 0; nt < 4; nt++)
            #pragma unroll
            for (int r = 0; r < 4; r++) acc[mt][nt][r] = 0.f;

    // prefetch tile 0
    float4 pa0 = *(const float4*)(Ag + (size_t)lr * K + lc);
    float4 pa1 = *(const float4*)(Ag + (size_t)(lr + 64) * K + lc);
    float4 pb0 = *(const float4*)(Bg + (size_t)lr * K + lc);
    float4 pb1 = *(const float4*)(Bg + (size_t)(lr + 64) * K + lc);

    for (int k0 = 0; k0 < K; k0 += BK) {
        // store prefetched tile (cvt to tf32)
        {
            uint2 u;
            u.x = f2tf(pa0.x); u.y = f2tf(pa0.y);
            *(uint2*)&As[lr][lc]      = u;
            u.x = f2tf(pa0.z); u.y = f2tf(pa0.w);
            *(uint2*)&As[lr][lc + 2]  = u;
            u.x = f2tf(pa1.x); u.y = f2tf(pa1.y);
            *(uint2*)&As[lr + 64][lc] = u;
            u.x = f2tf(pa1.z); u.y = f2tf(pa1.w);
            *(uint2*)&As[lr + 64][lc + 2] = u;
            u.x = f2tf(pb0.x); u.y = f2tf(pb0.y);
            *(uint2*)&Bs[lr][lc]      = u;
            u.x = f2tf(pb0.z); u.y = f2tf(pb0.w);
            *(uint2*)&Bs[lr][lc + 2]  = u;
            u.x = f2tf(pb1.x); u.y = f2tf(pb1.y);
            *(uint2*)&Bs[lr + 64][lc] = u;
            u.x = f2tf(pb1.z); u.y = f2tf(pb1.w);
            *(uint2*)&Bs[lr + 64][lc + 2] = u;
        }
        __syncthreads();

        if (k0 + BK < K) {
            const float* An = Ag + k0 + BK;
            const float* Bn = Bg + k0 + BK;
            pa0 = *(const float4*)(An + (size_t)lr * K + lc);
            pa1 = *(const float4*)(An + (size_t)(lr + 64) * K + lc);
            pb0 = *(const float4*)(Bn + (size_t)lr * K + lc);
            pb1 = *(const float4*)(Bn + (size_t)(lr + 64) * K + lc);
        }

        #pragma unroll
        for (int ks = 0; ks < 2; ks++) {
            unsigned af[4][4];
            #pragma unroll
            for (int mt = 0; mt < 4; mt++)
                ldmx4(af[mt][0], af[mt][1], af[mt][2], af[mt][3],
                      smem_u32(&As[arow + mt * 16][ks * 8 + acolo]));
            unsigned bf[2][4];
            #pragma unroll
            for (int p = 0; p < 2; p++)
                ldmx4(bf[p][0], bf[p][1], bf[p][2], bf[p][3],
                      smem_u32(&Bs[brow + p * 16][ks * 8 + bcolo]));
            #pragma unroll
            for (int mt = 0; mt < 4; mt++)
                #pragma unroll
                for (int nt = 0; nt < 4; nt++)
                    mma_tf32(acc[mt][nt], af[mt], &bf[nt >> 1][(nt & 1) * 2]);
        }
        __syncthreads();
    }

    // epilogue: thread holds (row g, col q*2) and (row g+8, col q*2) per tile
    const int g = lane >> 2, q = lane & 3;
    #pragma unroll
    for (int mt = 0; mt < 4; mt++) {
        #pragma unroll
        for (int nt = 0; nt < 4; nt++) {
            const int r0 = wm + mt * 16 + g;
            const int cc = wn + nt * 8 + q * 2;
            float d0 = acc[mt][nt][0], d1 = acc[mt][nt][1];
            float d2 = acc[mt][nt][2], d3 = acc[mt][nt][3];
            if (EPI >= 1) {
                const float b0 = biasp[cc], b1 = biasp[cc + 1];
                d0 += b0; d1 += b1; d2 += b0; d3 += b1;
            }
            if (EPI == 2) {
                const float* rp0 = Resid + (size_t)r0 * ldc + cc;
                const float* rp1 = Resid + (size_t)(r0 + 8) * ldc + cc;
                d0 += rp0[0]; d1 += rp0[1];
                d2 += rp1[0]; d3 += rp1[1];
            }
            if (EPI == 3) {
                d0 = gelu_exact(d0); d1 = gelu_exact(d1);
                d2 = gelu_exact(d2); d3 = gelu_exact(d3);
            }
            float2 v0 = make_float2(d0, d1);
            float2 v1 = make_float2(d2, d3);
            *(float2*)(C + (size_t)r0 * ldc + cc)       = v0;
            *(float2*)(C + (size_t)(r0 + 8) * ldc + cc) = v1;
        }
    }
}

// ---------------- driver -----------------------------------------------------
extern "C" void kernel_launch(void* const* d_in, const int* in_sizes, int n_in,
                              void* d_out, int out_size) {
    (void)in_sizes; (void)n_in; (void)out_size;
    const float* x     = (const float*)d_in[0];
    const float* ln1_w = (const float*)d_in[1];
    const float* ln1_b = (const float*)d_in[2];
    const float* qkv_w = (const float*)d_in[3];
    const float* qkv_b = (const float*)d_in[4];
    const float* out_w = (const float*)d_in[5];
    const float* out_b = (const float*)d_in[6];
    const float* ln2_w = (const float*)d_in[7];
    const float* ln2_b = (const float*)d_in[8];
    const float* w1    = (const float*)d_in[9];
    const float* b1    = (const float*)d_in[10];
    const float* w2    = (const float*)d_in[11];
    const float* b2    = (const float*)d_in[12];
    float* out = (float*)d_out;

    float *h, *qkv, *y, *x1, *h2, *mm;
    cudaGetSymbolAddress((void**)&h,   g_h);
    cudaGetSymbolAddress((void**)&qkv, g_qkv);
    cudaGetSymbolAddress((void**)&y,   g_y);
    cudaGetSymbolAddress((void**)&x1,  g_x1);
    cudaGetSymbolAddress((void**)&h2,  g_h2);
    cudaGetSymbolAddress((void**)&mm,  g_m);

    // 1. LN1
    ln_kernel<<<M_TOK, 256>>>(x, ln1_w, ln1_b, h);
    // 2. QKV = h @ qkv_w^T + qkv_b
    gemm_nt_tc<1><<<dim3(3 * D_MODEL / 128, M_TOK / 128), 256>>>(
        h, qkv_w, qkv, qkv_b, nullptr, D_MODEL, 3 * D_MODEL);
    // 3-5. fused causal attention -> y in [B,S,H*Dh] layout
    flash_attn<<<dim3(SEQLEN / BQ, BATCHSZ * N_HEADS), 256>>>(qkv, y);
    // 6. x1 = x + y @ out_w^T + out_b
    gemm_nt_tc<2><<<dim3(D_MODEL / 128, M_TOK / 128), 256>>>(
        y, out_w, x1, out_b, x, D_MODEL, D_MODEL);
    // 7. LN2
    ln_kernel<<<M_TOK, 256>>>(x1, ln2_w, ln2_b, h2);
    // 8. m = gelu(h2 @ w1^T + b1)
    gemm_nt_tc<3><<<dim3(D_FF / 128, M_TOK / 128), 256>>>(
        h2, w1, mm, b1, nullptr, D_MODEL, D_FF);
    // 9. out = x1 + m @ w2^T + b2
    gemm_nt_tc<2><<<dim3(D_MODEL / 128, M_TOK / 128), 256>>>(
        mm, w2, out, b2, x1, D_FF, D_MODEL);
}